// round 1
// baseline (speedup 1.0000x reference)
#include <cuda_runtime.h>
#include <cstdint>
#include <cstddef>

// ---------------- problem constants ----------------
#define C_INC   128
#define C_OUTC  256
#define HDIM    64
#define WDIM    64
#define BSZ     16
#define KKC     1152          // C_IN * 9
#define KWORDS  288           // KKC / 4 (int8 packed words)
#define M_TOT   65536         // BSZ * HDIM * WDIM
#define L_IMG   4096          // HDIM * WDIM

// GEMM tiling
#define BM   128
#define BN   128
#define BKW  16               // k-words per stage (64 int8 k-values)
#define KT_STEPS (KWORDS / BKW)   // 18

// ---------------- device scratch (allocation-free rule: __device__ globals) ----
__device__ float g_wscale[KKC];
__device__ float g_ascale[KKC];
__device__ float g_scale[KKC];
__device__ float g_qfx[KKC];          // 1 / (scale[j] * s_x)
__device__ float g_sx;
__device__ float g_sw;
__device__ __align__(16) int8_t g_wq[C_OUTC * KKC];
__device__ __align__(16) int8_t g_aq[(size_t)M_TOT * KKC];   // 75.5 MB

// ---------------- K1: per-column weight max --------------------------------
__global__ void k_wscale(const float* __restrict__ w) {
    int j = blockIdx.x * blockDim.x + threadIdx.x;
    if (j >= KKC) return;
    float m = 0.f;
    for (int o = 0; o < C_OUTC; ++o)
        m = fmaxf(m, fabsf(w[o * KKC + j]));
    g_wscale[j] = m;
}

// ---------------- K2: per (c,kh,kw) activation max via region masks ---------
// act_scale[c, kh, kw] = max |x[b,c,h,w]| over h,w restricted to the rows/cols
// that tap (kh,kw) actually touches (padding contributes only zeros).
__global__ void k_ascale(const float* __restrict__ x) {
    int c = blockIdx.x;
    float m[9];
#pragma unroll
    for (int v = 0; v < 9; ++v) m[v] = 0.f;

    for (int idx = threadIdx.x; idx < BSZ * L_IMG; idx += blockDim.x) {
        int b = idx >> 12;
        int p = idx & 4095;
        int h = p >> 6, w = p & 63;
        float a = fabsf(x[(((size_t)b * C_INC + c) << 12) + p]);
        bool h0 = (h < HDIM - 1);   // valid for kh = 0 (dh = -1)
        bool h2 = (h > 0);          // valid for kh = 2 (dh = +1)
        bool w0 = (w < WDIM - 1);
        bool w2 = (w > 0);
        if (h0 && w0) m[0] = fmaxf(m[0], a);
        if (h0)       m[1] = fmaxf(m[1], a);
        if (h0 && w2) m[2] = fmaxf(m[2], a);
        if (w0)       m[3] = fmaxf(m[3], a);
        m[4] = fmaxf(m[4], a);
        if (w2)       m[5] = fmaxf(m[5], a);
        if (h2 && w0) m[6] = fmaxf(m[6], a);
        if (h2)       m[7] = fmaxf(m[7], a);
        if (h2 && w2) m[8] = fmaxf(m[8], a);
    }

    __shared__ float sm[256];
    for (int v = 0; v < 9; ++v) {
        sm[threadIdx.x] = m[v];
        __syncthreads();
        for (int s = 128; s > 0; s >>= 1) {
            if (threadIdx.x < s)
                sm[threadIdx.x] = fmaxf(sm[threadIdx.x], sm[threadIdx.x + s]);
            __syncthreads();
        }
        if (threadIdx.x == 0) g_ascale[c * 9 + v] = sm[0];
        __syncthreads();
    }
}

// ---------------- K3: smooth scales + per-tensor quant scales ---------------
__global__ void k_scale() {
    __shared__ float red[256];
    __shared__ float s_sx_sh;
    int tid = threadIdx.x;

    float mx = 0.f, mw = 0.f;
    for (int j = tid; j < KKC; j += 256) {
        float a = g_ascale[j];
        float w = g_wscale[j];
        float s = __fdiv_rn(__fsqrt_rn(a), __fsqrt_rn(w));
        if (s == 0.f) s = 1.f;
        g_scale[j] = s;
        mx = fmaxf(mx, __fdiv_rn(a, s));   // == max |cols/scale| (monotone)
        mw = fmaxf(mw, w * s);             // == max |w2*scale|
    }

    red[tid] = mx; __syncthreads();
    for (int s = 128; s > 0; s >>= 1) {
        if (tid < s) red[tid] = fmaxf(red[tid], red[tid + s]);
        __syncthreads();
    }
    if (tid == 0) {
        float sx = __fdiv_rn(red[0], 127.f);
        if (sx == 0.f) sx = 1.f;
        g_sx = sx; s_sx_sh = sx;
    }
    __syncthreads();

    red[tid] = mw; __syncthreads();
    for (int s = 128; s > 0; s >>= 1) {
        if (tid < s) red[tid] = fmaxf(red[tid], red[tid + s]);
        __syncthreads();
    }
    if (tid == 0) {
        float sw = __fdiv_rn(red[0], 127.f);
        if (sw == 0.f) sw = 1.f;
        g_sw = sw;
    }
    __syncthreads();

    float sx = s_sx_sh;
    for (int j = tid; j < KKC; j += 256)
        g_qfx[j] = __fdiv_rn(1.f, g_scale[j] * sx);
}

// ---------------- K4: quantize weights --------------------------------------
__global__ void k_wq(const float* __restrict__ w) {
    int i = blockIdx.x * blockDim.x + threadIdx.x;
    if (i >= C_OUTC * KKC) return;
    int j = i % KKC;
    float t = w[i] * g_scale[j];
    float q = rintf(__fdiv_rn(t, g_sw));
    q = fminf(fmaxf(q, -127.f), 127.f);
    g_wq[i] = (int8_t)(int)q;
}

// ---------------- K5: fused im2col + activation quantization ----------------
// block = one output position r (b,h,w); 288 threads, each packs 4 columns.
__global__ void k_aq(const float* __restrict__ x) {
    int r = blockIdx.x;
    int b = r >> 12;
    int p = r & 4095;
    int h = p >> 6, w = p & 63;
    int j0 = threadIdx.x << 2;

    int qb[4];
#pragma unroll
    for (int e = 0; e < 4; ++e) {
        int j  = j0 + e;
        int c  = j / 9;
        int t  = j - c * 9;
        int kh = t / 3;
        int kw = t - kh * 3;
        int hi = h + kh - 1, wi = w + kw - 1;
        float v = 0.f;
        if ((unsigned)hi < (unsigned)HDIM && (unsigned)wi < (unsigned)WDIM)
            v = __ldg(&x[(((size_t)b * C_INC + c) << 12) + (hi << 6) + wi]);
        float q = rintf(v * __ldg(&g_qfx[j]));
        q = fminf(fmaxf(q, -127.f), 127.f);
        qb[e] = (int)q;
    }
    int packed = (qb[0] & 0xff) | ((qb[1] & 0xff) << 8) |
                 ((qb[2] & 0xff) << 16) | (qb[3] << 24);
    ((int*)g_aq)[(size_t)r * KWORDS + threadIdx.x] = packed;
}

// ---------------- K6: int8 dp4a GEMM + epilogue -----------------------------
// C[M,N] = Aq(int8) * Wq(int8)^T; out = C * (sx*sw) + bias, laid out NCHW.
__global__ void __launch_bounds__(256, 2) k_gemm(const float* __restrict__ bias,
                                                 float* __restrict__ out) {
    __shared__ int As[BM][BKW + 1];   // +1 pad -> conflict-free reads
    __shared__ int Bs[BN][BKW + 1];

    int tid = threadIdx.x;
    int m0 = blockIdx.x * BM;
    int n0 = blockIdx.y * BN;
    int tr = tid & 15, tc = tid >> 4;

    int acc[8][8];
#pragma unroll
    for (int i = 0; i < 8; ++i)
#pragma unroll
        for (int j = 0; j < 8; ++j) acc[i][j] = 0;

    const int4* Ag = (const int4*)g_aq;   // 72 int4 per row
    const int4* Bg = (const int4*)g_wq;

    for (int kt = 0; kt < KT_STEPS; ++kt) {
#pragma unroll
        for (int it = 0; it < 2; ++it) {
            int f4  = tid + it * 256;       // 512 int4 per tile
            int row = f4 >> 2;
            int c4  = f4 & 3;
            int4 va = Ag[(size_t)(m0 + row) * 72 + kt * 4 + c4];
            int4 vb = Bg[(size_t)(n0 + row) * 72 + kt * 4 + c4];
            int* ap = &As[row][c4 * 4];
            ap[0] = va.x; ap[1] = va.y; ap[2] = va.z; ap[3] = va.w;
            int* bp = &Bs[row][c4 * 4];
            bp[0] = vb.x; bp[1] = vb.y; bp[2] = vb.z; bp[3] = vb.w;
        }
        __syncthreads();

#pragma unroll 4
        for (int w = 0; w < BKW; ++w) {
            int a[8], b[8];
#pragma unroll
            for (int i = 0; i < 8; ++i) a[i] = As[tr + i * 16][w];
#pragma unroll
            for (int j = 0; j < 8; ++j) b[j] = Bs[tc + j * 16][w];
#pragma unroll
            for (int i = 0; i < 8; ++i)
#pragma unroll
                for (int j = 0; j < 8; ++j)
                    acc[i][j] = __dp4a(a[i], b[j], acc[i][j]);
        }
        __syncthreads();
    }

    float osc = g_sx * g_sw;
    int b_img = m0 >> 12;      // tile lies within one image (4096 % 128 == 0)
    int l0 = m0 & 4095;
#pragma unroll
    for (int j = 0; j < 8; ++j) {
        int o = n0 + tc + j * 16;
        float bz = bias[o];
        float* op = out + (((size_t)b_img * C_OUTC + o) << 12) + l0;
#pragma unroll
        for (int i = 0; i < 8; ++i)
            op[tr + i * 16] = (float)acc[i][j] * osc + bz;
    }
}

// ---------------- launch -----------------------------------------------------
extern "C" void kernel_launch(void* const* d_in, const int* in_sizes, int n_in,
                              void* d_out, int out_size) {
    const float* x    = (const float*)d_in[0];
    const float* wt   = (const float*)d_in[1];
    const float* bias = (const float*)d_in[2];
    float* out = (float*)d_out;

    k_wscale<<<(KKC + 255) / 256, 256>>>(wt);
    k_ascale<<<C_INC, 256>>>(x);
    k_scale<<<1, 256>>>();
    k_wq<<<(C_OUTC * KKC) / 256, 256>>>(wt);
    k_aq<<<M_TOT, KWORDS>>>(x);
    k_gemm<<<dim3(M_TOT / BM, C_OUTC / BN), 256>>>(bias, out);
}

// round 2
// speedup vs baseline: 1.0521x; 1.0521x over previous
#include <cuda_runtime.h>
#include <cstdint>
#include <cstddef>

// ---------------- problem constants ----------------
#define C_INC   128
#define C_OUTC  256
#define HDIM    64
#define WDIM    64
#define BSZ     16
#define KKC     1152          // C_IN * 9
#define KWORDS  288           // KKC / 4 (int8 packed words)
#define M_TOT   65536         // BSZ * HDIM * WDIM
#define L_IMG   4096          // HDIM * WDIM

// GEMM tiling
#define BM   128
#define BN   128
#define BKB  64               // k-bytes per stage
#define KT_STEPS (KKC / BKB)  // 18
#define ASTRIDE 80            // smem bytes per row (64 data + 16 pad)
#define ASTAGE  (BM * ASTRIDE) // 10240 B per stage per operand

// ---------------- device scratch (allocation-free rule) ----------------------
__device__ float g_wscale[KKC];
__device__ float g_ascale[KKC];
__device__ float g_scale[KKC];
__device__ float g_qfx[KKC];          // 1 / (scale[j] * s_x)
__device__ float g_sx;
__device__ float g_sw;
__device__ __align__(16) int8_t g_wq[C_OUTC * KKC];
__device__ __align__(16) int8_t g_aq[(size_t)M_TOT * KKC];   // 75.5 MB

// ---------------- K1: per-column weight max --------------------------------
__global__ void k_wscale(const float* __restrict__ w) {
    int j = blockIdx.x * blockDim.x + threadIdx.x;
    if (j >= KKC) return;
    float m = 0.f;
    for (int o = 0; o < C_OUTC; ++o)
        m = fmaxf(m, fabsf(w[o * KKC + j]));
    g_wscale[j] = m;
}

// ---------------- K2: per (c,kh,kw) activation max via region masks ---------
__global__ void k_ascale(const float* __restrict__ x) {
    int c = blockIdx.x;
    float m[9];
#pragma unroll
    for (int v = 0; v < 9; ++v) m[v] = 0.f;

    for (int idx = threadIdx.x; idx < BSZ * L_IMG; idx += blockDim.x) {
        int b = idx >> 12;
        int p = idx & 4095;
        int h = p >> 6, w = p & 63;
        float a = fabsf(x[(((size_t)b * C_INC + c) << 12) + p]);
        bool h0 = (h < HDIM - 1);
        bool h2 = (h > 0);
        bool w0 = (w < WDIM - 1);
        bool w2 = (w > 0);
        if (h0 && w0) m[0] = fmaxf(m[0], a);
        if (h0)       m[1] = fmaxf(m[1], a);
        if (h0 && w2) m[2] = fmaxf(m[2], a);
        if (w0)       m[3] = fmaxf(m[3], a);
        m[4] = fmaxf(m[4], a);
        if (w2)       m[5] = fmaxf(m[5], a);
        if (h2 && w0) m[6] = fmaxf(m[6], a);
        if (h2)       m[7] = fmaxf(m[7], a);
        if (h2 && w2) m[8] = fmaxf(m[8], a);
    }

    __shared__ float sm[256];
    for (int v = 0; v < 9; ++v) {
        sm[threadIdx.x] = m[v];
        __syncthreads();
        for (int s = 128; s > 0; s >>= 1) {
            if (threadIdx.x < s)
                sm[threadIdx.x] = fmaxf(sm[threadIdx.x], sm[threadIdx.x + s]);
            __syncthreads();
        }
        if (threadIdx.x == 0) g_ascale[c * 9 + v] = sm[0];
        __syncthreads();
    }
}

// ---------------- K3: smooth scales + per-tensor quant scales ---------------
__global__ void k_scale() {
    __shared__ float red[256];
    __shared__ float s_sx_sh;
    int tid = threadIdx.x;

    float mx = 0.f, mw = 0.f;
    for (int j = tid; j < KKC; j += 256) {
        float a = g_ascale[j];
        float w = g_wscale[j];
        float s = __fdiv_rn(__fsqrt_rn(a), __fsqrt_rn(w));
        if (s == 0.f) s = 1.f;
        g_scale[j] = s;
        mx = fmaxf(mx, __fdiv_rn(a, s));
        mw = fmaxf(mw, w * s);
    }

    red[tid] = mx; __syncthreads();
    for (int s = 128; s > 0; s >>= 1) {
        if (tid < s) red[tid] = fmaxf(red[tid], red[tid + s]);
        __syncthreads();
    }
    if (tid == 0) {
        float sx = __fdiv_rn(red[0], 127.f);
        if (sx == 0.f) sx = 1.f;
        g_sx = sx; s_sx_sh = sx;
    }
    __syncthreads();

    red[tid] = mw; __syncthreads();
    for (int s = 128; s > 0; s >>= 1) {
        if (tid < s) red[tid] = fmaxf(red[tid], red[tid + s]);
        __syncthreads();
    }
    if (tid == 0) {
        float sw = __fdiv_rn(red[0], 127.f);
        if (sw == 0.f) sw = 1.f;
        g_sw = sw;
    }
    __syncthreads();

    float sx = s_sx_sh;
    for (int j = tid; j < KKC; j += 256)
        g_qfx[j] = __fdiv_rn(1.f, g_scale[j] * sx);
}

// ---------------- K4: quantize weights --------------------------------------
__global__ void k_wq(const float* __restrict__ w) {
    int i = blockIdx.x * blockDim.x + threadIdx.x;
    if (i >= C_OUTC * KKC) return;
    int j = i % KKC;
    float t = w[i] * g_scale[j];
    float q = rintf(__fdiv_rn(t, g_sw));
    q = fminf(fmaxf(q, -127.f), 127.f);
    g_wq[i] = (int8_t)(int)q;
}

// ---------------- K5: fused im2col + activation quantization ----------------
__global__ void k_aq(const float* __restrict__ x) {
    int r = blockIdx.x;
    int b = r >> 12;
    int p = r & 4095;
    int h = p >> 6, w = p & 63;
    int j0 = threadIdx.x << 2;

    int qb[4];
#pragma unroll
    for (int e = 0; e < 4; ++e) {
        int j  = j0 + e;
        int c  = j / 9;
        int t  = j - c * 9;
        int kh = t / 3;
        int kw = t - kh * 3;
        int hi = h + kh - 1, wi = w + kw - 1;
        float v = 0.f;
        if ((unsigned)hi < (unsigned)HDIM && (unsigned)wi < (unsigned)WDIM)
            v = __ldg(&x[(((size_t)b * C_INC + c) << 12) + (hi << 6) + wi]);
        float q = rintf(v * __ldg(&g_qfx[j]));
        q = fminf(fmaxf(q, -127.f), 127.f);
        qb[e] = (int)q;
    }
    int packed = (qb[0] & 0xff) | ((qb[1] & 0xff) << 8) |
                 ((qb[2] & 0xff) << 16) | (qb[3] << 24);
    ((int*)g_aq)[(size_t)r * KWORDS + threadIdx.x] = packed;
}

// ---------------- K6: int8 tensor-core GEMM + epilogue ----------------------
// C[M,N] = Aq(int8) * Wq(int8)^T via mma.sync m16n8k32; out NCHW.
// 8 warps = 2(m) x 4(n); warp tile 64x32; cp.async 2-stage pipeline.

__device__ __forceinline__ void cp16(void* smem_dst, const void* gmem_src) {
    unsigned s = (unsigned)__cvta_generic_to_shared(smem_dst);
    asm volatile("cp.async.cg.shared.global [%0], [%1], 16;\n"
                 :: "r"(s), "l"(gmem_src));
}

__device__ __forceinline__ void mma_s8(int* c, const int* a, const int* b) {
    asm volatile(
        "mma.sync.aligned.m16n8k32.row.col.s32.s8.s8.s32 "
        "{%0,%1,%2,%3}, {%4,%5,%6,%7}, {%8,%9}, {%0,%1,%2,%3};\n"
        : "+r"(c[0]), "+r"(c[1]), "+r"(c[2]), "+r"(c[3])
        : "r"(a[0]), "r"(a[1]), "r"(a[2]), "r"(a[3]), "r"(b[0]), "r"(b[1]));
}

__global__ void __launch_bounds__(256, 2) k_gemm(const float* __restrict__ bias,
                                                 float* __restrict__ out) {
    __shared__ __align__(16) unsigned char sm[4 * ASTAGE];   // A[2 stages] B[2 stages]
    unsigned char* As = sm;
    unsigned char* Bs = sm + 2 * ASTAGE;

    int tid = threadIdx.x;
    int warpId = tid >> 5, lane = tid & 31;
    int grp = lane >> 2, tig = lane & 3;
    int wm = warpId & 1, wn = warpId >> 1;
    int m0 = blockIdx.x * BM;
    int n0 = blockIdx.y * BN;

    int acc[4][4][4];
#pragma unroll
    for (int i = 0; i < 4; ++i)
#pragma unroll
        for (int j = 0; j < 4; ++j)
#pragma unroll
            for (int r = 0; r < 4; ++r) acc[i][j][r] = 0;

    const int4* Ag = (const int4*)g_aq;   // 72 int4 per row
    const int4* Bg = (const int4*)g_wq;

    // ---- stage loader: 512 int4 per operand tile, 2 per thread ----
    auto load_stage = [&](int kt, int s) {
#pragma unroll
        for (int it = 0; it < 2; ++it) {
            int f4  = tid + it * 256;
            int row = f4 >> 2;
            int c4  = f4 & 3;
            cp16(As + s * ASTAGE + row * ASTRIDE + c4 * 16,
                 Ag + (size_t)(m0 + row) * 72 + kt * 4 + c4);
            cp16(Bs + s * ASTAGE + row * ASTRIDE + c4 * 16,
                 Bg + (size_t)(n0 + row) * 72 + kt * 4 + c4);
        }
        asm volatile("cp.async.commit_group;\n" ::: "memory");
    };

    load_stage(0, 0);

    for (int kt = 0; kt < KT_STEPS; ++kt) {
        if (kt + 1 < KT_STEPS) {
            load_stage(kt + 1, (kt + 1) & 1);
            asm volatile("cp.async.wait_group 1;\n" ::: "memory");
        } else {
            asm volatile("cp.async.wait_group 0;\n" ::: "memory");
        }
        __syncthreads();

        const unsigned char* Ab = As + (kt & 1) * ASTAGE;
        const unsigned char* Bb = Bs + (kt & 1) * ASTAGE;

#pragma unroll
        for (int ks = 0; ks < 2; ++ks) {
            int a[4][4], b[4][2];
#pragma unroll
            for (int i = 0; i < 4; ++i) {
                int row = wm * 64 + i * 16 + grp;
                const int* p  = (const int*)(Ab + row * ASTRIDE + ks * 32 + tig * 4);
                const int* p8 = (const int*)(Ab + (row + 8) * ASTRIDE + ks * 32 + tig * 4);
                a[i][0] = p[0];
                a[i][1] = p8[0];
                a[i][2] = p[4];      // +16 bytes
                a[i][3] = p8[4];
            }
#pragma unroll
            for (int j = 0; j < 4; ++j) {
                int nrow = wn * 32 + j * 8 + grp;
                const int* p = (const int*)(Bb + nrow * ASTRIDE + ks * 32 + tig * 4);
                b[j][0] = p[0];
                b[j][1] = p[4];
            }
#pragma unroll
            for (int i = 0; i < 4; ++i)
#pragma unroll
                for (int j = 0; j < 4; ++j)
                    mma_s8(acc[i][j], a[i], b[j]);
        }
        __syncthreads();
    }

    // ---- epilogue: smem transpose for coalesced NCHW stores ----
    float osc = g_sx * g_sw;
    int b_img = m0 >> 12;
    int l0 = m0 & 4095;
    float* Es = (float*)sm + warpId * (8 * 68);   // 544 floats/warp, stride 68

#pragma unroll
    for (int j = 0; j < 4; ++j) {
#pragma unroll
        for (int i = 0; i < 4; ++i) {
            int ml = i * 16 + grp;
            Es[(tig * 2 + 0) * 68 + ml]     = (float)acc[i][j][0];
            Es[(tig * 2 + 1) * 68 + ml]     = (float)acc[i][j][1];
            Es[(tig * 2 + 0) * 68 + ml + 8] = (float)acc[i][j][2];
            Es[(tig * 2 + 1) * 68 + ml + 8] = (float)acc[i][j][3];
        }
        __syncwarp();
#pragma unroll
        for (int n = 0; n < 8; ++n) {
            int o = n0 + wn * 32 + j * 8 + n;
            float bz = bias[o];
            float* op = out + (((size_t)b_img * C_OUTC + o) << 12) + l0 + wm * 64;
            op[lane]      = Es[n * 68 + lane]      * osc + bz;
            op[lane + 32] = Es[n * 68 + lane + 32] * osc + bz;
        }
        __syncwarp();
    }
}

// ---------------- launch -----------------------------------------------------
extern "C" void kernel_launch(void* const* d_in, const int* in_sizes, int n_in,
                              void* d_out, int out_size) {
    const float* x    = (const float*)d_in[0];
    const float* wt   = (const float*)d_in[1];
    const float* bias = (const float*)d_in[2];
    float* out = (float*)d_out;

    k_wscale<<<(KKC + 255) / 256, 256>>>(wt);
    k_ascale<<<C_INC, 256>>>(x);
    k_scale<<<1, 256>>>();
    k_wq<<<(C_OUTC * KKC) / 256, 256>>>(wt);
    k_aq<<<M_TOT, KWORDS>>>(x);
    k_gemm<<<dim3(M_TOT / BM, C_OUTC / BN), 256>>>(bias, out);
}

// round 3
// speedup vs baseline: 1.5362x; 1.4601x over previous
#include <cuda_runtime.h>
#include <cstdint>
#include <cstddef>

// ---------------- problem constants ----------------
#define C_INC   128
#define C_OUTC  256
#define HDIM    64
#define WDIM    64
#define BSZ     16
#define KKC     1152          // C_IN * 9
#define KWORDS  288           // KKC / 4
#define M_TOT   65536         // BSZ * HDIM * WDIM
#define L_IMG   4096

// GEMM tiling
#define BM   128
#define BN   128
#define BKB  64
#define KT_STEPS (KKC / BKB)  // 18
#define ASTRIDE 80
#define ASTAGE  (BM * ASTRIDE)

// k_aq staging
#define SSTR  1156            // smem A-strip row stride (289 words, gcd(289,32)=1)
#define AQ_SMEM (KKC*4 + 8*3*66*4 + 64*SSTR)   // 4608 + 6336 + 73984 = 84928

// ---------------- device scratch ----------------
__device__ float g_wscale[KKC];
__device__ float g_ascale[KKC];
__device__ float g_scale[KKC];
__device__ float g_qfx[KKC];
__device__ float g_sx;
__device__ float g_sw;
__device__ __align__(16) int8_t g_wq[C_OUTC * KKC];
__device__ __align__(16) int8_t g_aq[(size_t)M_TOT * KKC];

// ---------------- K1: weight per-column max (+ zero ascale accumulators) ----
__global__ void k_wscale(const float* __restrict__ w) {
    int j = blockIdx.x * blockDim.x + threadIdx.x;
    if (j >= KKC) return;
    g_ascale[j] = 0.f;                      // reset for atomicMax (every replay)
    float m = 0.f;
    for (int o = 0; o < C_OUTC; ++o)
        m = fmaxf(m, fabsf(w[o * KKC + j]));
    g_wscale[j] = m;
}

// ---------------- K2: activation per-(c,kh,kw) max, split over (c,b) --------
__global__ void k_ascale(const float* __restrict__ x) {
    int c = blockIdx.x, b = blockIdx.y;
    float m[9];
#pragma unroll
    for (int v = 0; v < 9; ++v) m[v] = 0.f;

    const float* xb = x + (((size_t)b * C_INC + c) << 12);
    for (int p = threadIdx.x; p < L_IMG; p += 256) {
        int h = p >> 6, w = p & 63;
        float a = fabsf(xb[p]);
        bool h0 = (h < HDIM - 1);
        bool h2 = (h > 0);
        bool w0 = (w < WDIM - 1);
        bool w2 = (w > 0);
        if (h0 && w0) m[0] = fmaxf(m[0], a);
        if (h0)       m[1] = fmaxf(m[1], a);
        if (h0 && w2) m[2] = fmaxf(m[2], a);
        if (w0)       m[3] = fmaxf(m[3], a);
        m[4] = fmaxf(m[4], a);
        if (w2)       m[5] = fmaxf(m[5], a);
        if (h2 && w0) m[6] = fmaxf(m[6], a);
        if (h2)       m[7] = fmaxf(m[7], a);
        if (h2 && w2) m[8] = fmaxf(m[8], a);
    }

    __shared__ float sm[256];
    for (int v = 0; v < 9; ++v) {
        sm[threadIdx.x] = m[v];
        __syncthreads();
        for (int s = 128; s > 0; s >>= 1) {
            if (threadIdx.x < s)
                sm[threadIdx.x] = fmaxf(sm[threadIdx.x], sm[threadIdx.x + s]);
            __syncthreads();
        }
        if (threadIdx.x == 0)   // values >= 0: int compare == float compare
            atomicMax((int*)&g_ascale[c * 9 + v], __float_as_int(sm[0]));
        __syncthreads();
    }
}

// ---------------- K3: smooth scales + per-tensor quant scales ---------------
__global__ void k_scale() {
    __shared__ float red[256];
    __shared__ float s_sx_sh;
    int tid = threadIdx.x;

    float mx = 0.f, mw = 0.f;
    for (int j = tid; j < KKC; j += 256) {
        float a = g_ascale[j];
        float w = g_wscale[j];
        float s = __fdiv_rn(__fsqrt_rn(a), __fsqrt_rn(w));
        if (s == 0.f) s = 1.f;
        g_scale[j] = s;
        mx = fmaxf(mx, __fdiv_rn(a, s));
        mw = fmaxf(mw, w * s);
    }

    red[tid] = mx; __syncthreads();
    for (int s = 128; s > 0; s >>= 1) {
        if (tid < s) red[tid] = fmaxf(red[tid], red[tid + s]);
        __syncthreads();
    }
    if (tid == 0) {
        float sx = __fdiv_rn(red[0], 127.f);
        if (sx == 0.f) sx = 1.f;
        g_sx = sx; s_sx_sh = sx;
    }
    __syncthreads();

    red[tid] = mw; __syncthreads();
    for (int s = 128; s > 0; s >>= 1) {
        if (tid < s) red[tid] = fmaxf(red[tid], red[tid + s]);
        __syncthreads();
    }
    if (tid == 0) {
        float sw = __fdiv_rn(red[0], 127.f);
        if (sw == 0.f) sw = 1.f;
        g_sw = sw;
    }
    __syncthreads();

    float sx = s_sx_sh;
    for (int j = tid; j < KKC; j += 256)
        g_qfx[j] = __fdiv_rn(1.f, g_scale[j] * sx);
}

// ---------------- K4: quantize weights --------------------------------------
__global__ void k_wq(const float* __restrict__ w) {
    int i = blockIdx.x * blockDim.x + threadIdx.x;
    if (i >= C_OUTC * KKC) return;
    int j = i % KKC;
    float t = w[i] * g_scale[j];
    float q = rintf(__fdiv_rn(t, g_sw));
    q = fminf(fmaxf(q, -127.f), 127.f);
    g_wq[i] = (int8_t)(int)q;
}

// ---------------- K5: fused im2col + quantization, smem-staged transpose ----
// block = one (b, h) strip of 64 output positions. Coalesced x reads,
// conflict-free smem byte stores (stride 1156), coalesced int writeout.
__global__ void __launch_bounds__(256) k_aq(const float* __restrict__ x) {
    extern __shared__ char dsm[];
    float*  qfx_s = (float*)dsm;                   // 1152
    float*  xs    = qfx_s + KKC;                   // 8 groups * 3 rows * 66
    int8_t* aqs   = (int8_t*)(xs + 8 * 3 * 66);    // 64 * SSTR

    int tid = threadIdx.x;
    int bh  = blockIdx.x;          // b*64 + h
    int b   = bh >> 6, h = bh & 63;
    int g   = tid >> 5, lane = tid & 31;

    for (int j = tid; j < KKC; j += 256) qfx_s[j] = g_qfx[j];

    float* xg = xs + g * (3 * 66);

    for (int c0 = 0; c0 < C_INC; c0 += 8) {
        int c = c0 + g;
        __syncthreads();           // xs reuse barrier (also covers qfx_s fill)
        const float* xb = x + (((size_t)b * C_INC + c) << 12);
#pragma unroll
        for (int r = 0; r < 3; ++r) {
            int hh = h + r - 1;
            float v0 = 0.f, v1 = 0.f;
            if ((unsigned)hh < (unsigned)HDIM) {
                v0 = xb[(hh << 6) + lane];
                v1 = xb[(hh << 6) + lane + 32];
            }
            xg[r * 66 + 1 + lane]  = v0;
            xg[r * 66 + 33 + lane] = v1;
            if (lane == 0) { xg[r * 66] = 0.f; xg[r * 66 + 65] = 0.f; }
        }
        __syncthreads();
#pragma unroll
        for (int half = 0; half < 2; ++half) {
            int w = lane + half * 32;
#pragma unroll
            for (int e = 0; e < 9; ++e) {
                const int kh = e / 3, kw = e % 3;
                float v = xg[kh * 66 + w + kw];
                float q = rintf(v * qfx_s[c * 9 + e]);
                q = fminf(fmaxf(q, -127.f), 127.f);
                aqs[w * SSTR + c * 9 + e] = (int8_t)(int)q;
            }
        }
    }
    __syncthreads();

    // writeout: 64 rows x 288 ints, coalesced
    int* dst = (int*)g_aq;
    for (int idx = tid; idx < 64 * KWORDS; idx += 256) {
        int row = idx / KWORDS;
        int col = idx - row * KWORDS;
        dst[((size_t)(bh * 64 + row)) * KWORDS + col] =
            *(const int*)(aqs + row * SSTR + col * 4);
    }
}

// ---------------- K6: int8 tensor-core GEMM + epilogue ----------------------
__device__ __forceinline__ void cp16(void* smem_dst, const void* gmem_src) {
    unsigned s = (unsigned)__cvta_generic_to_shared(smem_dst);
    asm volatile("cp.async.cg.shared.global [%0], [%1], 16;\n"
                 :: "r"(s), "l"(gmem_src));
}

__device__ __forceinline__ void mma_s8(int* c, const int* a, const int* b) {
    asm volatile(
        "mma.sync.aligned.m16n8k32.row.col.s32.s8.s8.s32 "
        "{%0,%1,%2,%3}, {%4,%5,%6,%7}, {%8,%9}, {%0,%1,%2,%3};\n"
        : "+r"(c[0]), "+r"(c[1]), "+r"(c[2]), "+r"(c[3])
        : "r"(a[0]), "r"(a[1]), "r"(a[2]), "r"(a[3]), "r"(b[0]), "r"(b[1]));
}

__global__ void __launch_bounds__(256, 2) k_gemm(const float* __restrict__ bias,
                                                 float* __restrict__ out) {
    __shared__ __align__(16) unsigned char sm[4 * ASTAGE];
    unsigned char* As = sm;
    unsigned char* Bs = sm + 2 * ASTAGE;

    int tid = threadIdx.x;
    int warpId = tid >> 5, lane = tid & 31;
    int grp = lane >> 2, tig = lane & 3;
    int wm = warpId & 1, wn = warpId >> 1;
    int m0 = blockIdx.x * BM;
    int n0 = blockIdx.y * BN;

    int acc[4][4][4];
#pragma unroll
    for (int i = 0; i < 4; ++i)
#pragma unroll
        for (int j = 0; j < 4; ++j)
#pragma unroll
            for (int r = 0; r < 4; ++r) acc[i][j][r] = 0;

    const int4* Ag = (const int4*)g_aq;
    const int4* Bg = (const int4*)g_wq;

    auto load_stage = [&](int kt, int s) {
#pragma unroll
        for (int it = 0; it < 2; ++it) {
            int f4  = tid + it * 256;
            int row = f4 >> 2;
            int c4  = f4 & 3;
            cp16(As + s * ASTAGE + row * ASTRIDE + c4 * 16,
                 Ag + (size_t)(m0 + row) * 72 + kt * 4 + c4);
            cp16(Bs + s * ASTAGE + row * ASTRIDE + c4 * 16,
                 Bg + (size_t)(n0 + row) * 72 + kt * 4 + c4);
        }
        asm volatile("cp.async.commit_group;\n" ::: "memory");
    };

    load_stage(0, 0);

    for (int kt = 0; kt < KT_STEPS; ++kt) {
        if (kt + 1 < KT_STEPS) {
            load_stage(kt + 1, (kt + 1) & 1);
            asm volatile("cp.async.wait_group 1;\n" ::: "memory");
        } else {
            asm volatile("cp.async.wait_group 0;\n" ::: "memory");
        }
        __syncthreads();

        const unsigned char* Ab = As + (kt & 1) * ASTAGE;
        const unsigned char* Bb = Bs + (kt & 1) * ASTAGE;

#pragma unroll
        for (int ks = 0; ks < 2; ++ks) {
            int a[4][4], b[4][2];
#pragma unroll
            for (int i = 0; i < 4; ++i) {
                int row = wm * 64 + i * 16 + grp;
                const int* p  = (const int*)(Ab + row * ASTRIDE + ks * 32 + tig * 4);
                const int* p8 = (const int*)(Ab + (row + 8) * ASTRIDE + ks * 32 + tig * 4);
                a[i][0] = p[0];
                a[i][1] = p8[0];
                a[i][2] = p[4];
                a[i][3] = p8[4];
            }
#pragma unroll
            for (int j = 0; j < 4; ++j) {
                int nrow = wn * 32 + j * 8 + grp;
                const int* p = (const int*)(Bb + nrow * ASTRIDE + ks * 32 + tig * 4);
                b[j][0] = p[0];
                b[j][1] = p[4];
            }
#pragma unroll
            for (int i = 0; i < 4; ++i)
#pragma unroll
                for (int j = 0; j < 4; ++j)
                    mma_s8(acc[i][j], a[i], b[j]);
        }
        __syncthreads();
    }

    // epilogue: smem transpose -> coalesced NCHW stores
    float osc = g_sx * g_sw;
    int b_img = m0 >> 12;
    int l0 = m0 & 4095;
    float* Es = (float*)sm + warpId * (8 * 68);

#pragma unroll
    for (int j = 0; j < 4; ++j) {
#pragma unroll
        for (int i = 0; i < 4; ++i) {
            int ml = i * 16 + grp;
            Es[(tig * 2 + 0) * 68 + ml]     = (float)acc[i][j][0];
            Es[(tig * 2 + 1) * 68 + ml]     = (float)acc[i][j][1];
            Es[(tig * 2 + 0) * 68 + ml + 8] = (float)acc[i][j][2];
            Es[(tig * 2 + 1) * 68 + ml + 8] = (float)acc[i][j][3];
        }
        __syncwarp();
#pragma unroll
        for (int n = 0; n < 8; ++n) {
            int o = n0 + wn * 32 + j * 8 + n;
            float bz = bias[o];
            float* op = out + (((size_t)b_img * C_OUTC + o) << 12) + l0 + wm * 64;
            op[lane]      = Es[n * 68 + lane]      * osc + bz;
            op[lane + 32] = Es[n * 68 + lane + 32] * osc + bz;
        }
        __syncwarp();
    }
}

// ---------------- launch -----------------------------------------------------
extern "C" void kernel_launch(void* const* d_in, const int* in_sizes, int n_in,
                              void* d_out, int out_size) {
    const float* x    = (const float*)d_in[0];
    const float* wt   = (const float*)d_in[1];
    const float* bias = (const float*)d_in[2];
    float* out = (float*)d_out;

    cudaFuncSetAttribute(k_aq, cudaFuncAttributeMaxDynamicSharedMemorySize,
                         AQ_SMEM);

    k_wscale<<<(KKC + 255) / 256, 256>>>(wt);
    k_ascale<<<dim3(C_INC, BSZ), 256>>>(x);
    k_scale<<<1, 256>>>();
    k_wq<<<(C_OUTC * KKC) / 256, 256>>>(wt);
    k_aq<<<BSZ * HDIM, 256, AQ_SMEM>>>(x);
    k_gemm<<<dim3(M_TOT / BM, C_OUTC / BN), 256>>>(bias, out);
}